// round 15
// baseline (speedup 1.0000x reference)
#include <cuda_runtime.h>
#include <cuda_fp16.h>
#include <cstdint>
#include <math.h>

#define NN 50000
#define EE 800000
#define HH 8
#define CC 16
#define HC 128       // H*C

// ---------------- scratch (device globals; no allocation allowed) ----------------
__device__ __align__(16) float  g_h1[(size_t)NN * HC];
__device__ __align__(16) float  g_hA[(size_t)NN * HC];
__device__ __align__(16) float  g_hB[(size_t)NN * HC];
__device__ __align__(16) float  g_z [(size_t)NN * HC];
__device__ __align__(16) __half g_zsh [(size_t)NN * HC];   // fp16 z_scale (edge_att gathers)
__device__ __align__(16) __half g_h16A[(size_t)NN * HC];   // fp16 mirror of g_hA
__device__ __align__(16) __half g_h16B[(size_t)NN * HC];   // fp16 mirror of g_hB
__device__ __align__(16) float  g_ae[(size_t)EE * HH];
__device__ float g_aself[(size_t)NN * HH];
__device__ float g_deg  [(size_t)NN * HH];
__device__ float g_dinv [(size_t)NN * HH];
// CSR build (g_cnt zero at load; scan resets it each launch -> replay-safe)
__device__ int  g_cnt[NN];
__device__ int  g_cur[NN];
__device__ int  g_off[NN + 1];
__device__ int  g_src[EE];
__device__ __align__(8) int2 g_edge[EE];   // (r, c) per CSR position

__device__ __forceinline__ float eluf(float x) {
    return x > 0.f ? x : __expf(x) - 1.f;
}
__device__ __forceinline__ float softplusf(float x) {
    return fmaxf(x, 0.f) + __logf(1.f + __expf(-fabsf(x)));
}
__device__ __forceinline__ float to_tf32(float x) {
    uint32_t u;
    asm("cvt.rna.tf32.f32 %0, %1;" : "=r"(u) : "f"(x));
    return __uint_as_float(u);
}
__device__ __forceinline__ void mma_tf32(float d[4], const float a[4], const float b[2]) {
    asm volatile(
        "mma.sync.aligned.m16n8k8.row.col.f32.tf32.tf32.f32 "
        "{%0,%1,%2,%3}, {%4,%5,%6,%7}, {%8,%9}, {%0,%1,%2,%3};\n"
        : "+f"(d[0]), "+f"(d[1]), "+f"(d[2]), "+f"(d[3])
        : "r"(__float_as_uint(a[0])), "r"(__float_as_uint(a[1])),
          "r"(__float_as_uint(a[2])), "r"(__float_as_uint(a[3])),
          "r"(__float_as_uint(b[0])), "r"(__float_as_uint(b[1])));
}
__device__ __forceinline__ void store_half4(__half* dst, float4 v) {
    __half2 a = __floats2half2_rn(v.x, v.y);
    __half2 b = __floats2half2_rn(v.z, v.w);
    uint2 u;
    u.x = *(unsigned*)&a; u.y = *(unsigned*)&b;
    *(uint2*)dst = u;
}
// 8 fp16 -> 8 fp32
__device__ __forceinline__ void cvt8(const uint4 u, float* f) {
    float2 a = __half22float2(*(__half2*)&u.x);
    float2 b = __half22float2(*(__half2*)&u.y);
    float2 c = __half22float2(*(__half2*)&u.z);
    float2 d = __half22float2(*(__half2*)&u.w);
    f[0]=a.x; f[1]=a.y; f[2]=b.x; f[3]=b.y; f[4]=c.x; f[5]=c.y; f[6]=d.x; f[7]=d.y;
}
__device__ __forceinline__ uint4 pack8(const float* f) {
    uint4 u;
    __half2 a = __floats2half2_rn(f[0], f[1]);
    __half2 b = __floats2half2_rn(f[2], f[3]);
    __half2 c = __floats2half2_rn(f[4], f[5]);
    __half2 d = __floats2half2_rn(f[6], f[7]);
    u.x = *(unsigned*)&a; u.y = *(unsigned*)&b;
    u.z = *(unsigned*)&c; u.w = *(unsigned*)&d;
    return u;
}

// ---------------- CSR build --------------------------------------------------------
__global__ void hist_kernel(const int* __restrict__ ei)
{
    int i = blockIdx.x * blockDim.x + threadIdx.x;
    int stride = gridDim.x * blockDim.x;
    for (int e = i; e < EE; e += stride) atomicAdd(&g_cnt[ei[EE + e]], 1);
}

__global__ void scan_kernel()   // single block, 1024 threads
{
    __shared__ int swarp[32];
    __shared__ int stot;
    int tid = threadIdx.x, lane = tid & 31, wid = tid >> 5;
    if (tid == 0) stot = 0;
    __syncthreads();
    for (int base = 0; base < NN; base += 1024) {
        int i = base + tid;
        int v = (i < NN) ? g_cnt[i] : 0;
        int x = v;
        #pragma unroll
        for (int d = 1; d < 32; d <<= 1) {
            int t = __shfl_up_sync(0xffffffffu, x, d);
            if (lane >= d) x += t;
        }
        if (lane == 31) swarp[wid] = x;
        __syncthreads();
        if (wid == 0) {
            int y = swarp[lane];
            int s = y;
            #pragma unroll
            for (int d = 1; d < 32; d <<= 1) {
                int t = __shfl_up_sync(0xffffffffu, s, d);
                if (lane >= d) s += t;
            }
            swarp[lane] = s - y;   // exclusive warp offset
        }
        __syncthreads();
        int excl = stot + swarp[wid] + x - v;
        if (i < NN) { g_off[i] = excl; g_cur[i] = excl; g_cnt[i] = 0; }
        __syncthreads();
        if (tid == 1023) stot = excl + v;
        __syncthreads();
    }
    if (tid == 0) g_off[NN] = EE;
}

__global__ void scatter_kernel(const int* __restrict__ ei)
{
    int i = blockIdx.x * blockDim.x + threadIdx.x;
    int stride = gridDim.x * blockDim.x;
    for (int e = i; e < EE; e += stride) {
        int c = ei[EE + e];
        int r = ei[e];
        int pos = atomicAdd(&g_cur[c], 1);
        g_src[pos] = r;
        g_edge[pos] = make_int2(r, c);
    }
}

// ---------------- GEMM1 (tf32 tensor cores): g_h1 = elu(x @ W0 + b0), K=256 --------
__global__ void __launch_bounds__(256) gemm1_tc(
    const float* __restrict__ A, const float* __restrict__ W,
    const float* __restrict__ bias)
{
    __shared__ float As[16][136];
    __shared__ float Bs[16][136];
    const int tid = threadIdx.x;
    const int warp = tid >> 5, lane = tid & 31;
    const int wm = (warp & 1) << 6;
    const int wn = (warp >> 1) << 5;
    const int block_row = blockIdx.x * 128;

    float acc[4][4][4];
    #pragma unroll
    for (int mt = 0; mt < 4; mt++)
        #pragma unroll
        for (int nt = 0; nt < 4; nt++)
            #pragma unroll
            for (int q = 0; q < 4; q++) acc[mt][nt][q] = 0.f;

    for (int k0 = 0; k0 < 256; k0 += 16) {
        #pragma unroll
        for (int i = 0; i < 2; i++) {
            int f = tid + (i << 8);
            int row = f >> 2, kk = (f & 3) << 2;
            int grow = block_row + row;
            float4 v = make_float4(0.f, 0.f, 0.f, 0.f);
            if (grow < NN) v = *(const float4*)&A[(size_t)grow * 256 + k0 + kk];
            As[kk + 0][row] = to_tf32(v.x);
            As[kk + 1][row] = to_tf32(v.y);
            As[kk + 2][row] = to_tf32(v.z);
            As[kk + 3][row] = to_tf32(v.w);
            int bk = f >> 5, n = (f & 31) << 2;
            float4 wv = *(const float4*)&W[(size_t)(k0 + bk) * HC + n];
            *(float4*)&Bs[bk][n] = make_float4(to_tf32(wv.x), to_tf32(wv.y),
                                               to_tf32(wv.z), to_tf32(wv.w));
        }
        __syncthreads();
        #pragma unroll
        for (int ks = 0; ks < 16; ks += 8) {
            float a[4][4];
            #pragma unroll
            for (int mt = 0; mt < 4; mt++) {
                int r0 = wm + (mt << 4) + (lane >> 2);
                int kl = ks + (lane & 3);
                a[mt][0] = As[kl][r0];
                a[mt][1] = As[kl][r0 + 8];
                a[mt][2] = As[kl + 4][r0];
                a[mt][3] = As[kl + 4][r0 + 8];
            }
            float b[4][2];
            #pragma unroll
            for (int nt = 0; nt < 4; nt++) {
                int c0 = wn + (nt << 3) + (lane >> 2);
                int kl = ks + (lane & 3);
                b[nt][0] = Bs[kl][c0];
                b[nt][1] = Bs[kl + 4][c0];
            }
            #pragma unroll
            for (int mt = 0; mt < 4; mt++)
                #pragma unroll
                for (int nt = 0; nt < 4; nt++)
                    mma_tf32(acc[mt][nt], a[mt], b[nt]);
        }
        __syncthreads();
    }
    #pragma unroll
    for (int mt = 0; mt < 4; mt++) {
        int r0 = block_row + wm + (mt << 4) + (lane >> 2);
        #pragma unroll
        for (int nt = 0; nt < 4; nt++) {
            int c = wn + (nt << 3) + ((lane & 3) << 1);
            float b0 = __ldg(&bias[c]), b1 = __ldg(&bias[c + 1]);
            if (r0 < NN) {
                g_h1[(size_t)r0 * HC + c]     = eluf(acc[mt][nt][0] + b0);
                g_h1[(size_t)r0 * HC + c + 1] = eluf(acc[mt][nt][1] + b1);
            }
            if (r0 + 8 < NN) {
                g_h1[(size_t)(r0 + 8) * HC + c]     = eluf(acc[mt][nt][2] + b0);
                g_h1[(size_t)(r0 + 8) * HC + c + 1] = eluf(acc[mt][nt][3] + b1);
            }
        }
    }
}

// ---------------- GEMM2 (tf32) + hop-0 epilogue + hop-1 self-attention -------------
__global__ void __launch_bounds__(256) gemm2_tc(
    const float* __restrict__ W, const float* __restrict__ bias,
    const float* __restrict__ hop_att0, const float* __restrict__ hop_bias0,
    const float* __restrict__ atts1, float decay0)
{
    __shared__ float As[16][72];
    __shared__ float Bs[16][136];
    __shared__ float hbuf[64][132];
    const int tid = threadIdx.x;
    const int warp = tid >> 5, lane = tid & 31;
    const int wm = (warp & 1) << 5;
    const int wn = (warp >> 1) << 5;
    const int block_row = blockIdx.x * 64;

    float acc[2][4][4];
    #pragma unroll
    for (int mt = 0; mt < 2; mt++)
        #pragma unroll
        for (int nt = 0; nt < 4; nt++)
            #pragma unroll
            for (int q = 0; q < 4; q++) acc[mt][nt][q] = 0.f;

    for (int k0 = 0; k0 < 128; k0 += 16) {
        {
            int row = tid >> 2, kk = (tid & 3) << 2;
            int grow = block_row + row;
            float4 v = make_float4(0.f, 0.f, 0.f, 0.f);
            if (grow < NN) v = *(const float4*)&g_h1[(size_t)grow * HC + k0 + kk];
            As[kk + 0][row] = to_tf32(v.x);
            As[kk + 1][row] = to_tf32(v.y);
            As[kk + 2][row] = to_tf32(v.z);
            As[kk + 3][row] = to_tf32(v.w);
        }
        #pragma unroll
        for (int i = 0; i < 2; i++) {
            int f = tid + (i << 8);
            int bk = f >> 5, n = (f & 31) << 2;
            float4 wv = *(const float4*)&W[(size_t)(k0 + bk) * HC + n];
            *(float4*)&Bs[bk][n] = make_float4(to_tf32(wv.x), to_tf32(wv.y),
                                               to_tf32(wv.z), to_tf32(wv.w));
        }
        __syncthreads();
        #pragma unroll
        for (int ks = 0; ks < 16; ks += 8) {
            float a[2][4];
            #pragma unroll
            for (int mt = 0; mt < 2; mt++) {
                int r0 = wm + (mt << 4) + (lane >> 2);
                int kl = ks + (lane & 3);
                a[mt][0] = As[kl][r0];
                a[mt][1] = As[kl][r0 + 8];
                a[mt][2] = As[kl + 4][r0];
                a[mt][3] = As[kl + 4][r0 + 8];
            }
            float b[4][2];
            #pragma unroll
            for (int nt = 0; nt < 4; nt++) {
                int c0 = wn + (nt << 3) + (lane >> 2);
                int kl = ks + (lane & 3);
                b[nt][0] = Bs[kl][c0];
                b[nt][1] = Bs[kl + 4][c0];
            }
            #pragma unroll
            for (int mt = 0; mt < 2; mt++)
                #pragma unroll
                for (int nt = 0; nt < 4; nt++)
                    mma_tf32(acc[mt][nt], a[mt], b[nt]);
        }
        __syncthreads();
    }
    #pragma unroll
    for (int mt = 0; mt < 2; mt++) {
        int r0 = wm + (mt << 4) + (lane >> 2);
        #pragma unroll
        for (int nt = 0; nt < 4; nt++) {
            int c = wn + (nt << 3) + ((lane & 3) << 1);
            float b0 = __ldg(&bias[c]), b1 = __ldg(&bias[c + 1]);
            hbuf[r0][c]         = acc[mt][nt][0] + b0;
            hbuf[r0][c + 1]     = acc[mt][nt][1] + b1;
            hbuf[r0 + 8][c]     = acc[mt][nt][2] + b0;
            hbuf[r0 + 8][c + 1] = acc[mt][nt][3] + b1;
        }
    }
    __syncthreads();
    const int head = lane >> 2, sub = lane & 3;
    const float* av = hop_att0 + head * CC + (sub << 2);
    const float av0 = av[0], av1 = av[1], av2 = av[2], av3 = av[3];
    const float* sv = atts1 + head * CC + (sub << 2);
    const float sv0 = sv[0], sv1 = sv[1], sv2 = sv[2], sv3 = sv[3];
    const float hb = hop_bias0[head];
    #pragma unroll
    for (int j = 0; j < 8; j++) {
        int row = (warp << 3) + j;
        int grow = block_row + row;
        if (grow < NN) {
            float4 h4 = *(float4*)&hbuf[row][lane << 2];
            float p = eluf(h4.x)*av0 + eluf(h4.y)*av1 + eluf(h4.z)*av2 + eluf(h4.w)*av3;
            p += __shfl_xor_sync(0xffffffffu, p, 1);
            p += __shfl_xor_sync(0xffffffffu, p, 2);
            float g = p + hb;
            size_t off = (size_t)grow * HC + (lane << 2);
            *(float4*)&g_hA[off] = h4;
            store_half4(&g_h16A[off], h4);
            float4 z4 = make_float4(h4.x*g, h4.y*g, h4.z*g, h4.w*g);
            *(float4*)&g_z[off] = z4;
            float4 zs4 = make_float4(z4.x*decay0, z4.y*decay0, z4.z*decay0, z4.w*decay0);
            store_half4(&g_zsh[off], zs4);
            float p2 = eluf(2.f*zs4.x)*sv0 + eluf(2.f*zs4.y)*sv1
                     + eluf(2.f*zs4.z)*sv2 + eluf(2.f*zs4.w)*sv3;
            p2 += __shfl_xor_sync(0xffffffffu, p2, 1);
            p2 += __shfl_xor_sync(0xffffffffu, p2, 2);
            if (sub == 0) {
                float a = softplusf(p2) + 1e-6f;
                g_aself[(size_t)grow * HH + head] = a;
                g_deg  [(size_t)grow * HH + head] = a;
            }
        }
    }
}

// ---------------- edge attention: QUARTER-warp per edge (4 edges/warp) -------------
// lane = q*8 + head: q = lane>>3 selects edge, head = lane&7 owns all 16 channels.
// Fully lane-local head reduction: no shfl, no predication.
__global__ void edge_att_kernel(const float* __restrict__ atts_k)
{
    const int lane = threadIdx.x & 31;
    const int warp0 = (blockIdx.x * blockDim.x + threadIdx.x) >> 5;
    const int nwarps = (gridDim.x * blockDim.x) >> 5;
    const int q = lane >> 3;
    const int head = lane & 7;

    float av[16];
    #pragma unroll
    for (int j = 0; j < 16; j += 4)
        *(float4*)&av[j] = *(const float4*)&atts_k[head * CC + j];

    const int NG = EE >> 2;   // 200000 groups of 4
    for (int gq = warp0; gq < NG; gq += nwarps) {
        int p = (gq << 2) + q;
        int2 rc = __ldg(&g_edge[p]);
        const __half* zc = &g_zsh[((unsigned)rc.y << 7) + (head << 4)];
        const __half* zr = &g_zsh[((unsigned)rc.x << 7) + (head << 4)];
        uint4 i0 = *(const uint4*)zc;
        uint4 i1 = *(const uint4*)(zc + 8);
        uint4 j0 = *(const uint4*)zr;
        uint4 j1 = *(const uint4*)(zr + 8);
        float fi[16], fj[16];
        cvt8(i0, fi); cvt8(i1, fi + 8);
        cvt8(j0, fj); cvt8(j1, fj + 8);
        float s = 0.f;
        #pragma unroll
        for (int j = 0; j < 16; j++) s += eluf(fi[j] + fj[j]) * av[j];
        float a = softplusf(s) + 1e-6f;
        g_ae[(size_t)p * HH + head] = a;
        atomicAdd(&g_deg[(size_t)rc.y * HH + head], a);
    }
}

// ---------------- dinv = rsqrt(deg) -------------------------------------------------
__global__ void dinv_kernel()
{
    int i = blockIdx.x * blockDim.x + threadIdx.x;
    if (i < NN * HH) g_dinv[i] = rsqrtf(g_deg[i]);
}

// ---------------- propagate + hop update: QUARTER-warp per node --------------------
// lane = q*8 + head; each quarter serially accumulates its node's CSR list,
// 16 channels per lane; epilogue fully lane-local.
__global__ void __launch_bounds__(256) prop_fused(
    const float* __restrict__ hop_atts_k,
    const float* __restrict__ hop_bias_k,
    const float* __restrict__ atts_next,
    float decay_prev, float decayk, int flip, int do_next)
{
    const float*  hp   = flip ? g_hA   : g_hB;
    const __half* hp16 = flip ? g_h16A : g_h16B;
    float*  hout   = flip ? g_hB   : g_hA;
    __half* hout16 = flip ? g_h16B : g_h16A;

    const int lane = threadIdx.x & 31;
    const int q = lane >> 3;
    const int head = lane & 7;
    int w = (((blockIdx.x * blockDim.x + threadIdx.x) >> 5) << 2) + q;
    if (w >= NN) return;
    const unsigned coff = ((unsigned)w << 7) + (head << 4);

    float dinv_c = g_dinv[w * HH + head];
    float acc[16];
    {
        float asn = g_aself[w * HH + head] * dinv_c;
        #pragma unroll
        for (int j = 0; j < 16; j += 4) {
            float4 v = *(const float4*)&hp[coff + j];
            acc[j]   = asn * v.x; acc[j+1] = asn * v.y;
            acc[j+2] = asn * v.z; acc[j+3] = asn * v.w;
        }
    }

    const int end = g_off[w + 1];
    int p = g_off[w];
    for (; p + 1 < end; p += 2) {
        int r0 = __ldg(&g_src[p]);
        int r1 = __ldg(&g_src[p + 1]);
        float a0 = __ldg(&g_ae[(size_t)(p    ) * HH + head]) * __ldg(&g_dinv[r0 * HH + head]);
        float a1 = __ldg(&g_ae[(size_t)(p + 1) * HH + head]) * __ldg(&g_dinv[r1 * HH + head]);
        const __half* s0 = &hp16[((unsigned)r0 << 7) + (head << 4)];
        const __half* s1 = &hp16[((unsigned)r1 << 7) + (head << 4)];
        uint4 u00 = *(const uint4*)s0;
        uint4 u01 = *(const uint4*)(s0 + 8);
        uint4 u10 = *(const uint4*)s1;
        uint4 u11 = *(const uint4*)(s1 + 8);
        float f0[16], f1[16];
        cvt8(u00, f0); cvt8(u01, f0 + 8);
        cvt8(u10, f1); cvt8(u11, f1 + 8);
        #pragma unroll
        for (int j = 0; j < 16; j++) acc[j] = fmaf(a0, f0[j], acc[j]);
        #pragma unroll
        for (int j = 0; j < 16; j++) acc[j] = fmaf(a1, f1[j], acc[j]);
    }
    if (p < end) {
        int r0 = __ldg(&g_src[p]);
        float a0 = __ldg(&g_ae[(size_t)p * HH + head]) * __ldg(&g_dinv[r0 * HH + head]);
        const __half* s0 = &hp16[((unsigned)r0 << 7) + (head << 4)];
        uint4 u00 = *(const uint4*)s0;
        uint4 u01 = *(const uint4*)(s0 + 8);
        float f0[16];
        cvt8(u00, f0); cvt8(u01, f0 + 8);
        #pragma unroll
        for (int j = 0; j < 16; j++) acc[j] = fmaf(a0, f0[j], acc[j]);
    }

    // ---- epilogue: all lane-local ----
    float h[16];
    #pragma unroll
    for (int j = 0; j < 16; j++) h[j] = acc[j] * dinv_c;
    #pragma unroll
    for (int j = 0; j < 16; j += 4)
        *(float4*)&hout[coff + j] = make_float4(h[j], h[j+1], h[j+2], h[j+3]);
    *(uint4*)&hout16[coff]     = pack8(h);
    *(uint4*)&hout16[coff + 8] = pack8(h + 8);

    float z[16];
    #pragma unroll
    for (int j = 0; j < 16; j += 4) {
        float4 v = *(const float4*)&g_z[coff + j];
        z[j] = v.x; z[j+1] = v.y; z[j+2] = v.z; z[j+3] = v.w;
    }
    const float* aw  = hop_atts_k + head * (2 * CC);
    const float* aw2 = aw + CC;
    float s = 0.f;
    #pragma unroll
    for (int j = 0; j < 16; j++)
        s += eluf(h[j]) * __ldg(&aw[j]) + eluf(z[j] * decay_prev) * __ldg(&aw2[j]);
    float g = s + __ldg(&hop_bias_k[head]);
    float zs[16];
    #pragma unroll
    for (int j = 0; j < 16; j++) {
        z[j] = fmaf(h[j], g, z[j]);
        zs[j] = z[j] * decayk;
    }
    #pragma unroll
    for (int j = 0; j < 16; j += 4)
        *(float4*)&g_z[coff + j] = make_float4(z[j], z[j+1], z[j+2], z[j+3]);
    *(uint4*)&g_zsh[coff]     = pack8(zs);
    *(uint4*)&g_zsh[coff + 8] = pack8(zs + 8);

    if (do_next) {
        const float* sv = atts_next + head * CC;
        float p2 = 0.f;
        #pragma unroll
        for (int j = 0; j < 16; j++) p2 += eluf(2.f * zs[j]) * __ldg(&sv[j]);
        float a = softplusf(p2) + 1e-6f;
        g_aself[w * HH + head] = a;
        g_deg  [w * HH + head] = a;
    }
}

// ---------------- output: out = elu(z) @ Wout + bout  (N x 40) --------------------
__global__ void out_kernel(const float* __restrict__ Wout,
                           const float* __restrict__ bout,
                           float* __restrict__ out)
{
    __shared__ float Ws[HC * 40];
    __shared__ float bs[40];
    __shared__ float zsm[8][HC];
    int tid = threadIdx.x;
    for (int i = tid; i < HC * 40; i += 320) Ws[i] = Wout[i];
    if (tid < 40) bs[tid] = bout[tid];
    int nbase = blockIdx.x * 8;
    for (int i = tid; i < 8 * HC; i += 320) {
        int ln = i >> 7, c = i & 127;
        int gn = nbase + ln;
        float v = (gn < NN) ? g_z[(size_t)gn * HC + c] : 0.f;
        zsm[ln][c] = eluf(v);
    }
    __syncthreads();
    int ln = tid / 40, o = tid % 40;
    if (ln < 8) {
        int gn = nbase + ln;
        if (gn < NN) {
            float acc = bs[o];
            #pragma unroll 8
            for (int c = 0; c < HC; c++) acc = fmaf(zsm[ln][c], Ws[c * 40 + o], acc);
            out[(size_t)gn * 40 + o] = acc;
        }
    }
}

// ---------------- host orchestration ----------------------------------------------
extern "C" void kernel_launch(void* const* d_in, const int* in_sizes, int n_in,
                              void* d_out, int out_size)
{
    const float* x          = (const float*)d_in[0];
    const int*   ei         = (const int*)d_in[1];
    const float* W0         = (const float*)d_in[2];
    const float* b0         = (const float*)d_in[3];
    const float* W1         = (const float*)d_in[4];
    const float* b1         = (const float*)d_in[5];
    const float* Wout       = (const float*)d_in[6];
    const float* bout       = (const float*)d_in[7];
    const float* hop_att0   = (const float*)d_in[8];
    const float* hop_atts   = (const float*)d_in[9];
    const float* atts       = (const float*)d_in[10];
    const float* hop_biases = (const float*)d_in[11];
    float* out = (float*)d_out;

    float decay[5];
    for (int k = 0; k <= 4; k++) decay[k] = (float)log(1.0 / (k + 1) + 1.0 + 1e-6);

    const int NODE_GRID4 = ((NN + 3) / 4 + 7) / 8;   // quarter-warp per node, 8 warps/blk
    const int EDGE_GRID = 12500;                      // 100k warps; 2 groups of 4 each

    hist_kernel<<<1024, 256>>>(ei);                                  // idx 0
    scan_kernel<<<1, 1024>>>();                                      // idx 1
    gemm1_tc<<<(NN + 127) / 128, 256>>>(x, W0, b0);                  // idx 2
    gemm2_tc<<<(NN + 63) / 64, 256>>>(W1, b1, hop_att0, hop_biases,
                                      atts, decay[0]);               // idx 3 (profiled)
    scatter_kernel<<<1024, 256>>>(ei);                               // idx 4

    for (int k = 1; k <= 4; k++) {
        int flip = (k & 1);
        edge_att_kernel<<<EDGE_GRID, 256>>>(atts + (size_t)(k - 1) * HH * CC);
        dinv_kernel<<<(NN * HH + 255) / 256, 256>>>();
        prop_fused<<<NODE_GRID4, 256>>>(hop_atts + (size_t)(k - 1) * HH * 2 * CC,
                                        hop_biases + (size_t)k * HH,
                                        atts + (size_t)k * HH * CC,
                                        decay[k - 1], decay[k], flip,
                                        (k < 4) ? 1 : 0);
    }

    out_kernel<<<(NN + 7) / 8, 320>>>(Wout, bout, out);
}

// round 16
// speedup vs baseline: 1.0330x; 1.0330x over previous
#include <cuda_runtime.h>
#include <cuda_fp16.h>
#include <cstdint>
#include <math.h>

#define NN 50000
#define EE 800000
#define HH 8
#define CC 16
#define HC 128       // H*C

// ---------------- scratch (device globals; no allocation allowed) ----------------
__device__ __align__(16) float  g_h1[(size_t)NN * HC];
__device__ __align__(16) float  g_hA[(size_t)NN * HC];
__device__ __align__(16) float  g_hB[(size_t)NN * HC];
__device__ __align__(16) float  g_z [(size_t)NN * HC];
__device__ __align__(16) __half g_zsh [(size_t)NN * HC];   // fp16 z_scale (edge_att gathers)
__device__ __align__(16) __half g_h16A[(size_t)NN * HC];   // fp16 mirror of g_hA
__device__ __align__(16) __half g_h16B[(size_t)NN * HC];   // fp16 mirror of g_hB
__device__ __align__(16) float  g_ae[(size_t)EE * HH];
__device__ float g_aself[(size_t)NN * HH];
__device__ float g_deg  [(size_t)NN * HH];
__device__ float g_dinv [(size_t)NN * HH];
// CSR build (g_cnt zero at load; scan resets it each launch -> replay-safe)
__device__ int  g_cnt[NN];
__device__ int  g_cur[NN];
__device__ int  g_off[NN + 1];
__device__ int  g_src[EE];
__device__ __align__(8) int2 g_edge[EE];   // (r, c) per CSR position

__device__ __forceinline__ float eluf(float x) {
    return x > 0.f ? x : __expf(x) - 1.f;
}
__device__ __forceinline__ float softplusf(float x) {
    return fmaxf(x, 0.f) + __logf(1.f + __expf(-fabsf(x)));
}
__device__ __forceinline__ float to_tf32(float x) {
    uint32_t u;
    asm("cvt.rna.tf32.f32 %0, %1;" : "=r"(u) : "f"(x));
    return __uint_as_float(u);
}
__device__ __forceinline__ void mma_tf32(float d[4], const float a[4], const float b[2]) {
    asm volatile(
        "mma.sync.aligned.m16n8k8.row.col.f32.tf32.tf32.f32 "
        "{%0,%1,%2,%3}, {%4,%5,%6,%7}, {%8,%9}, {%0,%1,%2,%3};\n"
        : "+f"(d[0]), "+f"(d[1]), "+f"(d[2]), "+f"(d[3])
        : "r"(__float_as_uint(a[0])), "r"(__float_as_uint(a[1])),
          "r"(__float_as_uint(a[2])), "r"(__float_as_uint(a[3])),
          "r"(__float_as_uint(b[0])), "r"(__float_as_uint(b[1])));
}
__device__ __forceinline__ void store_half4(__half* dst, float4 v) {
    __half2 a = __floats2half2_rn(v.x, v.y);
    __half2 b = __floats2half2_rn(v.z, v.w);
    uint2 u;
    u.x = *(unsigned*)&a; u.y = *(unsigned*)&b;
    *(uint2*)dst = u;
}
__device__ __forceinline__ float4 load_half4(const __half* src) {
    uint2 u = *(const uint2*)src;
    float2 lo = __half22float2(*(__half2*)&u.x);
    float2 hi = __half22float2(*(__half2*)&u.y);
    return make_float4(lo.x, lo.y, hi.x, hi.y);
}

// ---------------- CSR build --------------------------------------------------------
__global__ void hist_kernel(const int* __restrict__ ei)
{
    int i = blockIdx.x * blockDim.x + threadIdx.x;
    int stride = gridDim.x * blockDim.x;
    for (int e = i; e < EE; e += stride) atomicAdd(&g_cnt[ei[EE + e]], 1);
}

__global__ void scan_kernel()   // single block, 1024 threads
{
    __shared__ int swarp[32];
    __shared__ int stot;
    int tid = threadIdx.x, lane = tid & 31, wid = tid >> 5;
    if (tid == 0) stot = 0;
    __syncthreads();
    for (int base = 0; base < NN; base += 1024) {
        int i = base + tid;
        int v = (i < NN) ? g_cnt[i] : 0;
        int x = v;
        #pragma unroll
        for (int d = 1; d < 32; d <<= 1) {
            int t = __shfl_up_sync(0xffffffffu, x, d);
            if (lane >= d) x += t;
        }
        if (lane == 31) swarp[wid] = x;
        __syncthreads();
        if (wid == 0) {
            int y = swarp[lane];
            int s = y;
            #pragma unroll
            for (int d = 1; d < 32; d <<= 1) {
                int t = __shfl_up_sync(0xffffffffu, s, d);
                if (lane >= d) s += t;
            }
            swarp[lane] = s - y;   // exclusive warp offset
        }
        __syncthreads();
        int excl = stot + swarp[wid] + x - v;
        if (i < NN) { g_off[i] = excl; g_cur[i] = excl; g_cnt[i] = 0; }
        __syncthreads();
        if (tid == 1023) stot = excl + v;
        __syncthreads();
    }
    if (tid == 0) g_off[NN] = EE;
}

__global__ void scatter_kernel(const int* __restrict__ ei)
{
    int i = blockIdx.x * blockDim.x + threadIdx.x;
    int stride = gridDim.x * blockDim.x;
    for (int e = i; e < EE; e += stride) {
        int c = ei[EE + e];
        int r = ei[e];
        int pos = atomicAdd(&g_cur[c], 1);
        g_src[pos] = r;
        g_edge[pos] = make_int2(r, c);
    }
}

// ---------------- GEMM1 (tf32 tensor cores): g_h1 = elu(x @ W0 + b0), K=256 --------
__global__ void __launch_bounds__(256) gemm1_tc(
    const float* __restrict__ A, const float* __restrict__ W,
    const float* __restrict__ bias)
{
    __shared__ float As[16][136];
    __shared__ float Bs[16][136];
    const int tid = threadIdx.x;
    const int warp = tid >> 5, lane = tid & 31;
    const int wm = (warp & 1) << 6;
    const int wn = (warp >> 1) << 5;
    const int block_row = blockIdx.x * 128;

    float acc[4][4][4];
    #pragma unroll
    for (int mt = 0; mt < 4; mt++)
        #pragma unroll
        for (int nt = 0; nt < 4; nt++)
            #pragma unroll
            for (int q = 0; q < 4; q++) acc[mt][nt][q] = 0.f;

    for (int k0 = 0; k0 < 256; k0 += 16) {
        #pragma unroll
        for (int i = 0; i < 2; i++) {
            int f = tid + (i << 8);
            int row = f >> 2, kk = (f & 3) << 2;
            int grow = block_row + row;
            float4 v = make_float4(0.f, 0.f, 0.f, 0.f);
            if (grow < NN) v = *(const float4*)&A[(size_t)grow * 256 + k0 + kk];
            As[kk + 0][row] = to_tf32(v.x);
            As[kk + 1][row] = to_tf32(v.y);
            As[kk + 2][row] = to_tf32(v.z);
            As[kk + 3][row] = to_tf32(v.w);
            int bk = f >> 5, n = (f & 31) << 2;
            float4 wv = *(const float4*)&W[(size_t)(k0 + bk) * HC + n];
            *(float4*)&Bs[bk][n] = make_float4(to_tf32(wv.x), to_tf32(wv.y),
                                               to_tf32(wv.z), to_tf32(wv.w));
        }
        __syncthreads();
        #pragma unroll
        for (int ks = 0; ks < 16; ks += 8) {
            float a[4][4];
            #pragma unroll
            for (int mt = 0; mt < 4; mt++) {
                int r0 = wm + (mt << 4) + (lane >> 2);
                int kl = ks + (lane & 3);
                a[mt][0] = As[kl][r0];
                a[mt][1] = As[kl][r0 + 8];
                a[mt][2] = As[kl + 4][r0];
                a[mt][3] = As[kl + 4][r0 + 8];
            }
            float b[4][2];
            #pragma unroll
            for (int nt = 0; nt < 4; nt++) {
                int c0 = wn + (nt << 3) + (lane >> 2);
                int kl = ks + (lane & 3);
                b[nt][0] = Bs[kl][c0];
                b[nt][1] = Bs[kl + 4][c0];
            }
            #pragma unroll
            for (int mt = 0; mt < 4; mt++)
                #pragma unroll
                for (int nt = 0; nt < 4; nt++)
                    mma_tf32(acc[mt][nt], a[mt], b[nt]);
        }
        __syncthreads();
    }
    #pragma unroll
    for (int mt = 0; mt < 4; mt++) {
        int r0 = block_row + wm + (mt << 4) + (lane >> 2);
        #pragma unroll
        for (int nt = 0; nt < 4; nt++) {
            int c = wn + (nt << 3) + ((lane & 3) << 1);
            float b0 = __ldg(&bias[c]), b1 = __ldg(&bias[c + 1]);
            if (r0 < NN) {
                g_h1[(size_t)r0 * HC + c]     = eluf(acc[mt][nt][0] + b0);
                g_h1[(size_t)r0 * HC + c + 1] = eluf(acc[mt][nt][1] + b1);
            }
            if (r0 + 8 < NN) {
                g_h1[(size_t)(r0 + 8) * HC + c]     = eluf(acc[mt][nt][2] + b0);
                g_h1[(size_t)(r0 + 8) * HC + c + 1] = eluf(acc[mt][nt][3] + b1);
            }
        }
    }
}

// ---------------- GEMM2 (tf32) + hop-0 epilogue + hop-1 self-attention -------------
__global__ void __launch_bounds__(256) gemm2_tc(
    const float* __restrict__ W, const float* __restrict__ bias,
    const float* __restrict__ hop_att0, const float* __restrict__ hop_bias0,
    const float* __restrict__ atts1, float decay0)
{
    __shared__ float As[16][72];
    __shared__ float Bs[16][136];
    __shared__ float hbuf[64][132];
    const int tid = threadIdx.x;
    const int warp = tid >> 5, lane = tid & 31;
    const int wm = (warp & 1) << 5;
    const int wn = (warp >> 1) << 5;
    const int block_row = blockIdx.x * 64;

    float acc[2][4][4];
    #pragma unroll
    for (int mt = 0; mt < 2; mt++)
        #pragma unroll
        for (int nt = 0; nt < 4; nt++)
            #pragma unroll
            for (int q = 0; q < 4; q++) acc[mt][nt][q] = 0.f;

    for (int k0 = 0; k0 < 128; k0 += 16) {
        {
            int row = tid >> 2, kk = (tid & 3) << 2;
            int grow = block_row + row;
            float4 v = make_float4(0.f, 0.f, 0.f, 0.f);
            if (grow < NN) v = *(const float4*)&g_h1[(size_t)grow * HC + k0 + kk];
            As[kk + 0][row] = to_tf32(v.x);
            As[kk + 1][row] = to_tf32(v.y);
            As[kk + 2][row] = to_tf32(v.z);
            As[kk + 3][row] = to_tf32(v.w);
        }
        #pragma unroll
        for (int i = 0; i < 2; i++) {
            int f = tid + (i << 8);
            int bk = f >> 5, n = (f & 31) << 2;
            float4 wv = *(const float4*)&W[(size_t)(k0 + bk) * HC + n];
            *(float4*)&Bs[bk][n] = make_float4(to_tf32(wv.x), to_tf32(wv.y),
                                               to_tf32(wv.z), to_tf32(wv.w));
        }
        __syncthreads();
        #pragma unroll
        for (int ks = 0; ks < 16; ks += 8) {
            float a[2][4];
            #pragma unroll
            for (int mt = 0; mt < 2; mt++) {
                int r0 = wm + (mt << 4) + (lane >> 2);
                int kl = ks + (lane & 3);
                a[mt][0] = As[kl][r0];
                a[mt][1] = As[kl][r0 + 8];
                a[mt][2] = As[kl + 4][r0];
                a[mt][3] = As[kl + 4][r0 + 8];
            }
            float b[4][2];
            #pragma unroll
            for (int nt = 0; nt < 4; nt++) {
                int c0 = wn + (nt << 3) + (lane >> 2);
                int kl = ks + (lane & 3);
                b[nt][0] = Bs[kl][c0];
                b[nt][1] = Bs[kl + 4][c0];
            }
            #pragma unroll
            for (int mt = 0; mt < 2; mt++)
                #pragma unroll
                for (int nt = 0; nt < 4; nt++)
                    mma_tf32(acc[mt][nt], a[mt], b[nt]);
        }
        __syncthreads();
    }
    #pragma unroll
    for (int mt = 0; mt < 2; mt++) {
        int r0 = wm + (mt << 4) + (lane >> 2);
        #pragma unroll
        for (int nt = 0; nt < 4; nt++) {
            int c = wn + (nt << 3) + ((lane & 3) << 1);
            float b0 = __ldg(&bias[c]), b1 = __ldg(&bias[c + 1]);
            hbuf[r0][c]         = acc[mt][nt][0] + b0;
            hbuf[r0][c + 1]     = acc[mt][nt][1] + b1;
            hbuf[r0 + 8][c]     = acc[mt][nt][2] + b0;
            hbuf[r0 + 8][c + 1] = acc[mt][nt][3] + b1;
        }
    }
    __syncthreads();
    const int head = lane >> 2, sub = lane & 3;
    const float* av = hop_att0 + head * CC + (sub << 2);
    const float av0 = av[0], av1 = av[1], av2 = av[2], av3 = av[3];
    const float* sv = atts1 + head * CC + (sub << 2);
    const float sv0 = sv[0], sv1 = sv[1], sv2 = sv[2], sv3 = sv[3];
    const float hb = hop_bias0[head];
    #pragma unroll
    for (int j = 0; j < 8; j++) {
        int row = (warp << 3) + j;
        int grow = block_row + row;
        if (grow < NN) {
            float4 h4 = *(float4*)&hbuf[row][lane << 2];
            float p = eluf(h4.x)*av0 + eluf(h4.y)*av1 + eluf(h4.z)*av2 + eluf(h4.w)*av3;
            p += __shfl_xor_sync(0xffffffffu, p, 1);
            p += __shfl_xor_sync(0xffffffffu, p, 2);
            float g = p + hb;
            size_t off = (size_t)grow * HC + (lane << 2);
            *(float4*)&g_hA[off] = h4;
            store_half4(&g_h16A[off], h4);
            float4 z4 = make_float4(h4.x*g, h4.y*g, h4.z*g, h4.w*g);
            *(float4*)&g_z[off] = z4;
            float4 zs4 = make_float4(z4.x*decay0, z4.y*decay0, z4.z*decay0, z4.w*decay0);
            store_half4(&g_zsh[off], zs4);
            float p2 = eluf(2.f*zs4.x)*sv0 + eluf(2.f*zs4.y)*sv1
                     + eluf(2.f*zs4.z)*sv2 + eluf(2.f*zs4.w)*sv3;
            p2 += __shfl_xor_sync(0xffffffffu, p2, 1);
            p2 += __shfl_xor_sync(0xffffffffu, p2, 2);
            if (sub == 0) {
                float a = softplusf(p2) + 1e-6f;
                g_aself[(size_t)grow * HH + head] = a;
                g_deg  [(size_t)grow * HH + head] = a;
            }
        }
    }
}

// ---------------- edge attention: HALF-warp per edge, 2 pairs per iteration --------
__global__ void edge_att_kernel(const float* __restrict__ atts_k)
{
    const int lane = threadIdx.x & 31;
    const int warp0 = (blockIdx.x * blockDim.x + threadIdx.x) >> 5;
    const int nwarps = (gridDim.x * blockDim.x) >> 5;
    const int half = lane >> 4;
    const int sl = lane & 15;
    const int head = sl >> 1;
    const float* av = atts_k + head * CC + ((sl & 1) << 3);
    float4 avl = *(const float4*)av;
    float4 avh = *(const float4*)(av + 4);

    const int NPAIR = EE >> 1;   // 400000
    int q = warp0;
    for (; q + nwarps < NPAIR; q += 2 * nwarps) {
        int p0 = (q << 1) + half;
        int p1 = ((q + nwarps) << 1) + half;
        int2 rc0 = __ldg(&g_edge[p0]);
        int2 rc1 = __ldg(&g_edge[p1]);
        const uint4 i0 = *(const uint4*)&g_zsh[((unsigned)rc0.y << 7) + (sl << 3)];
        const uint4 j0 = *(const uint4*)&g_zsh[((unsigned)rc0.x << 7) + (sl << 3)];
        const uint4 i1 = *(const uint4*)&g_zsh[((unsigned)rc1.y << 7) + (sl << 3)];
        const uint4 j1 = *(const uint4*)&g_zsh[((unsigned)rc1.x << 7) + (sl << 3)];
        // edge 0
        {
            __half2 s0 = __hadd2(*(__half2*)&i0.x, *(__half2*)&j0.x);
            __half2 s1 = __hadd2(*(__half2*)&i0.y, *(__half2*)&j0.y);
            __half2 s2 = __hadd2(*(__half2*)&i0.z, *(__half2*)&j0.z);
            __half2 s3 = __hadd2(*(__half2*)&i0.w, *(__half2*)&j0.w);
            float2 f0 = __half22float2(s0);
            float2 f1 = __half22float2(s1);
            float2 f2 = __half22float2(s2);
            float2 f3 = __half22float2(s3);
            float s = eluf(f0.x)*avl.x + eluf(f0.y)*avl.y
                    + eluf(f1.x)*avl.z + eluf(f1.y)*avl.w
                    + eluf(f2.x)*avh.x + eluf(f2.y)*avh.y
                    + eluf(f3.x)*avh.z + eluf(f3.y)*avh.w;
            s += __shfl_xor_sync(0xffffffffu, s, 1);
            if (!(sl & 1)) {
                float a = softplusf(s) + 1e-6f;
                g_ae[(size_t)p0 * HH + head] = a;
                atomicAdd(&g_deg[(size_t)rc0.y * HH + head], a);
            }
        }
        // edge 1
        {
            __half2 s0 = __hadd2(*(__half2*)&i1.x, *(__half2*)&j1.x);
            __half2 s1 = __hadd2(*(__half2*)&i1.y, *(__half2*)&j1.y);
            __half2 s2 = __hadd2(*(__half2*)&i1.z, *(__half2*)&j1.z);
            __half2 s3 = __hadd2(*(__half2*)&i1.w, *(__half2*)&j1.w);
            float2 f0 = __half22float2(s0);
            float2 f1 = __half22float2(s1);
            float2 f2 = __half22float2(s2);
            float2 f3 = __half22float2(s3);
            float s = eluf(f0.x)*avl.x + eluf(f0.y)*avl.y
                    + eluf(f1.x)*avl.z + eluf(f1.y)*avl.w
                    + eluf(f2.x)*avh.x + eluf(f2.y)*avh.y
                    + eluf(f3.x)*avh.z + eluf(f3.y)*avh.w;
            s += __shfl_xor_sync(0xffffffffu, s, 1);
            if (!(sl & 1)) {
                float a = softplusf(s) + 1e-6f;
                g_ae[(size_t)p1 * HH + head] = a;
                atomicAdd(&g_deg[(size_t)rc1.y * HH + head], a);
            }
        }
    }
    for (; q < NPAIR; q += nwarps) {
        int p = (q << 1) + half;
        int2 rc = __ldg(&g_edge[p]);
        const uint4 ui = *(const uint4*)&g_zsh[((unsigned)rc.y << 7) + (sl << 3)];
        const uint4 uj = *(const uint4*)&g_zsh[((unsigned)rc.x << 7) + (sl << 3)];
        __half2 s0 = __hadd2(*(__half2*)&ui.x, *(__half2*)&uj.x);
        __half2 s1 = __hadd2(*(__half2*)&ui.y, *(__half2*)&uj.y);
        __half2 s2 = __hadd2(*(__half2*)&ui.z, *(__half2*)&uj.z);
        __half2 s3 = __hadd2(*(__half2*)&ui.w, *(__half2*)&uj.w);
        float2 f0 = __half22float2(s0);
        float2 f1 = __half22float2(s1);
        float2 f2 = __half22float2(s2);
        float2 f3 = __half22float2(s3);
        float s = eluf(f0.x)*avl.x + eluf(f0.y)*avl.y
                + eluf(f1.x)*avl.z + eluf(f1.y)*avl.w
                + eluf(f2.x)*avh.x + eluf(f2.y)*avh.y
                + eluf(f3.x)*avh.z + eluf(f3.y)*avh.w;
        s += __shfl_xor_sync(0xffffffffu, s, 1);
        if (!(sl & 1)) {
            float a = softplusf(s) + 1e-6f;
            g_ae[(size_t)p * HH + head] = a;
            atomicAdd(&g_deg[(size_t)rc.y * HH + head], a);
        }
    }
}

// ---------------- dinv = rsqrt(deg) -------------------------------------------------
__global__ void dinv_kernel()
{
    int i = blockIdx.x * blockDim.x + threadIdx.x;
    if (i < NN * HH) g_dinv[i] = rsqrtf(g_deg[i]);
}

// ---------------- propagate + hop update (fused; fp16 gathers, pipelined unroll 8) --
__global__ void prop_fused(const float* __restrict__ hop_atts_k,
                           const float* __restrict__ hop_bias_k,
                           const float* __restrict__ atts_next,
                           float decay_prev, float decayk, int flip, int do_next)
{
    const float*  hp   = flip ? g_hA   : g_hB;
    const __half* hp16 = flip ? g_h16A : g_h16B;
    float*  hout   = flip ? g_hB   : g_hA;
    __half* hout16 = flip ? g_h16B : g_h16A;
    int w = (blockIdx.x * blockDim.x + threadIdx.x) >> 5;
    if (w >= NN) return;
    const int lane = threadIdx.x & 31;
    const int head = lane >> 2, sub = lane & 3;
    const unsigned coff = ((unsigned)w << 7) + (lane << 2);

    float dinv_c = g_dinv[w * HH + head];
    float asn = g_aself[w * HH + head] * dinv_c;
    float4 hc = *(const float4*)&hp[coff];
    float4 acc = make_float4(asn*hc.x, asn*hc.y, asn*hc.z, asn*hc.w);

    const int beg = g_off[w], end = g_off[w + 1];
    int p = beg;
    int rrA[8];
    bool haveA = (p + 7 < end);
    if (haveA) {
        #pragma unroll
        for (int u = 0; u < 8; u++) rrA[u] = __ldg(&g_src[p + u]);
    }
    while (haveA) {
        int pn = p + 8;
        // issue current batch's payload loads
        uint2 hv[8];
        #pragma unroll
        for (int u = 0; u < 8; u++)
            hv[u] = *(const uint2*)&hp16[((unsigned)rrA[u] << 7) + (lane << 2)];
        float aa[8];
        #pragma unroll
        for (int u = 0; u < 8; u++)
            aa[u] = __ldg(&g_ae[(size_t)(p + u) * HH + head])
                  * __ldg(&g_dinv[rrA[u] * HH + head]);
        // prefetch next batch's indices while FMAs retire
        int rrB[8];
        bool haveB = (pn + 7 < end);
        if (haveB) {
            #pragma unroll
            for (int u = 0; u < 8; u++) rrB[u] = __ldg(&g_src[pn + u]);
        }
        #pragma unroll
        for (int u = 0; u < 8; u++) {
            float2 lo = __half22float2(*(__half2*)&hv[u].x);
            float2 hi = __half22float2(*(__half2*)&hv[u].y);
            acc.x = fmaf(aa[u], lo.x, acc.x); acc.y = fmaf(aa[u], lo.y, acc.y);
            acc.z = fmaf(aa[u], hi.x, acc.z); acc.w = fmaf(aa[u], hi.y, acc.w);
        }
        #pragma unroll
        for (int u = 0; u < 8; u++) rrA[u] = rrB[u];
        p = pn;
        haveA = haveB;
    }
    for (; p < end; p++) {
        int r0 = __ldg(&g_src[p]);
        float a0 = __ldg(&g_ae[(size_t)p * HH + head]) * __ldg(&g_dinv[r0 * HH + head]);
        float4 h0 = load_half4(&hp16[((unsigned)r0 << 7) + (lane << 2)]);
        acc.x = fmaf(a0, h0.x, acc.x); acc.y = fmaf(a0, h0.y, acc.y);
        acc.z = fmaf(a0, h0.z, acc.z); acc.w = fmaf(a0, h0.w, acc.w);
    }

    float4 h4 = make_float4(acc.x*dinv_c, acc.y*dinv_c, acc.z*dinv_c, acc.w*dinv_c);
    *(float4*)&hout[coff] = h4;
    store_half4(&hout16[coff], h4);

    // hop attention + z update
    float4 z4 = *(const float4*)&g_z[coff];
    float4 zp = make_float4(z4.x*decay_prev, z4.y*decay_prev,
                            z4.z*decay_prev, z4.w*decay_prev);
    const float* aw  = hop_atts_k + head * (2 * CC) + (sub << 2);
    const float* aw2 = aw + CC;
    float s = eluf(h4.x)*aw[0]  + eluf(h4.y)*aw[1]  + eluf(h4.z)*aw[2]  + eluf(h4.w)*aw[3]
            + eluf(zp.x)*aw2[0] + eluf(zp.y)*aw2[1] + eluf(zp.z)*aw2[2] + eluf(zp.w)*aw2[3];
    s += __shfl_xor_sync(0xffffffffu, s, 1);
    s += __shfl_xor_sync(0xffffffffu, s, 2);
    float g = s + hop_bias_k[head];
    z4.x = fmaf(h4.x, g, z4.x);
    z4.y = fmaf(h4.y, g, z4.y);
    z4.z = fmaf(h4.z, g, z4.z);
    z4.w = fmaf(h4.w, g, z4.w);
    *(float4*)&g_z[coff] = z4;
    float4 zs4 = make_float4(z4.x*decayk, z4.y*decayk, z4.z*decayk, z4.w*decayk);
    store_half4(&g_zsh[coff], zs4);

    if (do_next) {
        const float* sv = atts_next + head * CC + (sub << 2);
        float p2 = eluf(2.f*zs4.x)*sv[0] + eluf(2.f*zs4.y)*sv[1]
                 + eluf(2.f*zs4.z)*sv[2] + eluf(2.f*zs4.w)*sv[3];
        p2 += __shfl_xor_sync(0xffffffffu, p2, 1);
        p2 += __shfl_xor_sync(0xffffffffu, p2, 2);
        if (sub == 0) {
            float a = softplusf(p2) + 1e-6f;
            g_aself[w * HH + head] = a;
            g_deg  [w * HH + head] = a;
        }
    }
}

// ---------------- output: out = elu(z) @ Wout + bout  (N x 40) --------------------
__global__ void out_kernel(const float* __restrict__ Wout,
                           const float* __restrict__ bout,
                           float* __restrict__ out)
{
    __shared__ float Ws[HC * 40];
    __shared__ float bs[40];
    __shared__ float zsm[8][HC];
    int tid = threadIdx.x;
    for (int i = tid; i < HC * 40; i += 320) Ws[i] = Wout[i];
    if (tid < 40) bs[tid] = bout[tid];
    int nbase = blockIdx.x * 8;
    for (int i = tid; i < 8 * HC; i += 320) {
        int ln = i >> 7, c = i & 127;
        int gn = nbase + ln;
        float v = (gn < NN) ? g_z[(size_t)gn * HC + c] : 0.f;
        zsm[ln][c] = eluf(v);
    }
    __syncthreads();
    int ln = tid / 40, o = tid % 40;
    if (ln < 8) {
        int gn = nbase + ln;
        if (gn < NN) {
            float acc = bs[o];
            #pragma unroll 8
            for (int c = 0; c < HC; c++) acc = fmaf(zsm[ln][c], Ws[c * 40 + o], acc);
            out[(size_t)gn * 40 + o] = acc;
        }
    }
}

// ---------------- host orchestration ----------------------------------------------
extern "C" void kernel_launch(void* const* d_in, const int* in_sizes, int n_in,
                              void* d_out, int out_size)
{
    const float* x          = (const float*)d_in[0];
    const int*   ei         = (const int*)d_in[1];
    const float* W0         = (const float*)d_in[2];
    const float* b0         = (const float*)d_in[3];
    const float* W1         = (const float*)d_in[4];
    const float* b1         = (const float*)d_in[5];
    const float* Wout       = (const float*)d_in[6];
    const float* bout       = (const float*)d_in[7];
    const float* hop_att0   = (const float*)d_in[8];
    const float* hop_atts   = (const float*)d_in[9];
    const float* atts       = (const float*)d_in[10];
    const float* hop_biases = (const float*)d_in[11];
    float* out = (float*)d_out;

    float decay[5];
    for (int k = 0; k <= 4; k++) decay[k] = (float)log(1.0 / (k + 1) + 1.0 + 1e-6);

    const int NODE_GRID = (NN + 7) / 8;          // warp per node, 8 warps/block
    const int EDGE_GRID = 12500;                 // 100k warps

    hist_kernel<<<1024, 256>>>(ei);                                  // idx 0
    scan_kernel<<<1, 1024>>>();                                      // idx 1
    gemm1_tc<<<(NN + 127) / 128, 256>>>(x, W0, b0);                  // idx 2
    gemm2_tc<<<(NN + 63) / 64, 256>>>(W1, b1, hop_att0, hop_biases,
                                      atts, decay[0]);               // idx 3 (profiled)
    scatter_kernel<<<1024, 256>>>(ei);                               // idx 4

    for (int k = 1; k <= 4; k++) {
        int flip = (k & 1);
        edge_att_kernel<<<EDGE_GRID, 256>>>(atts + (size_t)(k - 1) * HH * CC);
        dinv_kernel<<<(NN * HH + 255) / 256, 256>>>();
        prop_fused<<<NODE_GRID, 256>>>(hop_atts + (size_t)(k - 1) * HH * 2 * CC,
                                       hop_biases + (size_t)k * HH,
                                       atts + (size_t)k * HH * CC,
                                       decay[k - 1], decay[k], flip,
                                       (k < 4) ? 1 : 0);
    }

    out_kernel<<<(NN + 7) / 8, 320>>>(Wout, bout, out);
}

// round 17
// speedup vs baseline: 1.0711x; 1.0368x over previous
#include <cuda_runtime.h>
#include <cuda_fp16.h>
#include <cstdint>
#include <math.h>

#define NN 50000
#define EE 800000
#define HH 8
#define CC 16
#define HC 128       // H*C

// ---------------- scratch (device globals; no allocation allowed) ----------------
__device__ __align__(16) float  g_h1[(size_t)NN * HC];
__device__ __align__(16) float  g_hA[(size_t)NN * HC];
__device__ __align__(16) float  g_hB[(size_t)NN * HC];
__device__ __align__(16) float  g_z [(size_t)NN * HC];
__device__ __align__(16) __half g_zsh [(size_t)NN * HC];   // fp16 z_scale (edge_att gathers)
__device__ __align__(16) __half g_h16A[(size_t)NN * HC];   // fp16 mirror of g_hA
__device__ __align__(16) __half g_h16B[(size_t)NN * HC];   // fp16 mirror of g_hB
__device__ __align__(16) float  g_ae[(size_t)EE * HH];
__device__ float g_aself[(size_t)NN * HH];
__device__ float g_deg  [(size_t)NN * HH];
__device__ float g_dinv [(size_t)NN * HH];
// CSR build (g_cnt zero at load; scan resets it each launch -> replay-safe)
__device__ int  g_cnt[NN];
__device__ int  g_cur[NN];
__device__ int  g_off[NN + 1];
__device__ int  g_src[EE];
__device__ __align__(8) int2 g_edge[EE];   // (r, c) per CSR position

__device__ __forceinline__ float eluf(float x) {
    return x > 0.f ? x : __expf(x) - 1.f;
}
__device__ __forceinline__ float softplusf(float x) {
    return fmaxf(x, 0.f) + __logf(1.f + __expf(-fabsf(x)));
}
__device__ __forceinline__ float to_tf32(float x) {
    uint32_t u;
    asm("cvt.rna.tf32.f32 %0, %1;" : "=r"(u) : "f"(x));
    return __uint_as_float(u);
}
__device__ __forceinline__ void mma_tf32(float d[4], const float a[4], const float b[2]) {
    asm volatile(
        "mma.sync.aligned.m16n8k8.row.col.f32.tf32.tf32.f32 "
        "{%0,%1,%2,%3}, {%4,%5,%6,%7}, {%8,%9}, {%0,%1,%2,%3};\n"
        : "+f"(d[0]), "+f"(d[1]), "+f"(d[2]), "+f"(d[3])
        : "r"(__float_as_uint(a[0])), "r"(__float_as_uint(a[1])),
          "r"(__float_as_uint(a[2])), "r"(__float_as_uint(a[3])),
          "r"(__float_as_uint(b[0])), "r"(__float_as_uint(b[1])));
}
__device__ __forceinline__ void store_half4(__half* dst, float4 v) {
    __half2 a = __floats2half2_rn(v.x, v.y);
    __half2 b = __floats2half2_rn(v.z, v.w);
    uint2 u;
    u.x = *(unsigned*)&a; u.y = *(unsigned*)&b;
    *(uint2*)dst = u;
}
__device__ __forceinline__ float4 load_half4(const __half* src) {
    uint2 u = *(const uint2*)src;
    float2 lo = __half22float2(*(__half2*)&u.x);
    float2 hi = __half22float2(*(__half2*)&u.y);
    return make_float4(lo.x, lo.y, hi.x, hi.y);
}

// ---------------- CSR build --------------------------------------------------------
__global__ void hist_kernel(const int* __restrict__ ei)
{
    int i = blockIdx.x * blockDim.x + threadIdx.x;
    int stride = gridDim.x * blockDim.x;
    for (int e = i; e < EE; e += stride) atomicAdd(&g_cnt[ei[EE + e]], 1);
}

__global__ void scan_kernel()   // single block, 1024 threads
{
    __shared__ int swarp[32];
    __shared__ int stot;
    int tid = threadIdx.x, lane = tid & 31, wid = tid >> 5;
    if (tid == 0) stot = 0;
    __syncthreads();
    for (int base = 0; base < NN; base += 1024) {
        int i = base + tid;
        int v = (i < NN) ? g_cnt[i] : 0;
        int x = v;
        #pragma unroll
        for (int d = 1; d < 32; d <<= 1) {
            int t = __shfl_up_sync(0xffffffffu, x, d);
            if (lane >= d) x += t;
        }
        if (lane == 31) swarp[wid] = x;
        __syncthreads();
        if (wid == 0) {
            int y = swarp[lane];
            int s = y;
            #pragma unroll
            for (int d = 1; d < 32; d <<= 1) {
                int t = __shfl_up_sync(0xffffffffu, s, d);
                if (lane >= d) s += t;
            }
            swarp[lane] = s - y;   // exclusive warp offset
        }
        __syncthreads();
        int excl = stot + swarp[wid] + x - v;
        if (i < NN) { g_off[i] = excl; g_cur[i] = excl; g_cnt[i] = 0; }
        __syncthreads();
        if (tid == 1023) stot = excl + v;
        __syncthreads();
    }
    if (tid == 0) g_off[NN] = EE;
}

__global__ void scatter_kernel(const int* __restrict__ ei)
{
    int i = blockIdx.x * blockDim.x + threadIdx.x;
    int stride = gridDim.x * blockDim.x;
    for (int e = i; e < EE; e += stride) {
        int c = ei[EE + e];
        int r = ei[e];
        int pos = atomicAdd(&g_cur[c], 1);
        g_src[pos] = r;
        g_edge[pos] = make_int2(r, c);
    }
}

// ---------------- GEMM1 (tf32 tensor cores): g_h1 = elu(x @ W0 + b0), K=256 --------
__global__ void __launch_bounds__(256) gemm1_tc(
    const float* __restrict__ A, const float* __restrict__ W,
    const float* __restrict__ bias)
{
    __shared__ float As[16][136];
    __shared__ float Bs[16][136];
    const int tid = threadIdx.x;
    const int warp = tid >> 5, lane = tid & 31;
    const int wm = (warp & 1) << 6;
    const int wn = (warp >> 1) << 5;
    const int block_row = blockIdx.x * 128;

    float acc[4][4][4];
    #pragma unroll
    for (int mt = 0; mt < 4; mt++)
        #pragma unroll
        for (int nt = 0; nt < 4; nt++)
            #pragma unroll
            for (int q = 0; q < 4; q++) acc[mt][nt][q] = 0.f;

    for (int k0 = 0; k0 < 256; k0 += 16) {
        #pragma unroll
        for (int i = 0; i < 2; i++) {
            int f = tid + (i << 8);
            int row = f >> 2, kk = (f & 3) << 2;
            int grow = block_row + row;
            float4 v = make_float4(0.f, 0.f, 0.f, 0.f);
            if (grow < NN) v = *(const float4*)&A[(size_t)grow * 256 + k0 + kk];
            As[kk + 0][row] = to_tf32(v.x);
            As[kk + 1][row] = to_tf32(v.y);
            As[kk + 2][row] = to_tf32(v.z);
            As[kk + 3][row] = to_tf32(v.w);
            int bk = f >> 5, n = (f & 31) << 2;
            float4 wv = *(const float4*)&W[(size_t)(k0 + bk) * HC + n];
            *(float4*)&Bs[bk][n] = make_float4(to_tf32(wv.x), to_tf32(wv.y),
                                               to_tf32(wv.z), to_tf32(wv.w));
        }
        __syncthreads();
        #pragma unroll
        for (int ks = 0; ks < 16; ks += 8) {
            float a[4][4];
            #pragma unroll
            for (int mt = 0; mt < 4; mt++) {
                int r0 = wm + (mt << 4) + (lane >> 2);
                int kl = ks + (lane & 3);
                a[mt][0] = As[kl][r0];
                a[mt][1] = As[kl][r0 + 8];
                a[mt][2] = As[kl + 4][r0];
                a[mt][3] = As[kl + 4][r0 + 8];
            }
            float b[4][2];
            #pragma unroll
            for (int nt = 0; nt < 4; nt++) {
                int c0 = wn + (nt << 3) + (lane >> 2);
                int kl = ks + (lane & 3);
                b[nt][0] = Bs[kl][c0];
                b[nt][1] = Bs[kl + 4][c0];
            }
            #pragma unroll
            for (int mt = 0; mt < 4; mt++)
                #pragma unroll
                for (int nt = 0; nt < 4; nt++)
                    mma_tf32(acc[mt][nt], a[mt], b[nt]);
        }
        __syncthreads();
    }
    #pragma unroll
    for (int mt = 0; mt < 4; mt++) {
        int r0 = block_row + wm + (mt << 4) + (lane >> 2);
        #pragma unroll
        for (int nt = 0; nt < 4; nt++) {
            int c = wn + (nt << 3) + ((lane & 3) << 1);
            float b0 = __ldg(&bias[c]), b1 = __ldg(&bias[c + 1]);
            if (r0 < NN) {
                g_h1[(size_t)r0 * HC + c]     = eluf(acc[mt][nt][0] + b0);
                g_h1[(size_t)r0 * HC + c + 1] = eluf(acc[mt][nt][1] + b1);
            }
            if (r0 + 8 < NN) {
                g_h1[(size_t)(r0 + 8) * HC + c]     = eluf(acc[mt][nt][2] + b0);
                g_h1[(size_t)(r0 + 8) * HC + c + 1] = eluf(acc[mt][nt][3] + b1);
            }
        }
    }
}

// ---------------- GEMM2 (tf32) + hop-0 epilogue + hop-1 self-attention -------------
__global__ void __launch_bounds__(256) gemm2_tc(
    const float* __restrict__ W, const float* __restrict__ bias,
    const float* __restrict__ hop_att0, const float* __restrict__ hop_bias0,
    const float* __restrict__ atts1, float decay0)
{
    __shared__ float As[16][72];
    __shared__ float Bs[16][136];
    __shared__ float hbuf[64][132];
    const int tid = threadIdx.x;
    const int warp = tid >> 5, lane = tid & 31;
    const int wm = (warp & 1) << 5;
    const int wn = (warp >> 1) << 5;
    const int block_row = blockIdx.x * 64;

    float acc[2][4][4];
    #pragma unroll
    for (int mt = 0; mt < 2; mt++)
        #pragma unroll
        for (int nt = 0; nt < 4; nt++)
            #pragma unroll
            for (int q = 0; q < 4; q++) acc[mt][nt][q] = 0.f;

    for (int k0 = 0; k0 < 128; k0 += 16) {
        {
            int row = tid >> 2, kk = (tid & 3) << 2;
            int grow = block_row + row;
            float4 v = make_float4(0.f, 0.f, 0.f, 0.f);
            if (grow < NN) v = *(const float4*)&g_h1[(size_t)grow * HC + k0 + kk];
            As[kk + 0][row] = to_tf32(v.x);
            As[kk + 1][row] = to_tf32(v.y);
            As[kk + 2][row] = to_tf32(v.z);
            As[kk + 3][row] = to_tf32(v.w);
        }
        #pragma unroll
        for (int i = 0; i < 2; i++) {
            int f = tid + (i << 8);
            int bk = f >> 5, n = (f & 31) << 2;
            float4 wv = *(const float4*)&W[(size_t)(k0 + bk) * HC + n];
            *(float4*)&Bs[bk][n] = make_float4(to_tf32(wv.x), to_tf32(wv.y),
                                               to_tf32(wv.z), to_tf32(wv.w));
        }
        __syncthreads();
        #pragma unroll
        for (int ks = 0; ks < 16; ks += 8) {
            float a[2][4];
            #pragma unroll
            for (int mt = 0; mt < 2; mt++) {
                int r0 = wm + (mt << 4) + (lane >> 2);
                int kl = ks + (lane & 3);
                a[mt][0] = As[kl][r0];
                a[mt][1] = As[kl][r0 + 8];
                a[mt][2] = As[kl + 4][r0];
                a[mt][3] = As[kl + 4][r0 + 8];
            }
            float b[4][2];
            #pragma unroll
            for (int nt = 0; nt < 4; nt++) {
                int c0 = wn + (nt << 3) + (lane >> 2);
                int kl = ks + (lane & 3);
                b[nt][0] = Bs[kl][c0];
                b[nt][1] = Bs[kl + 4][c0];
            }
            #pragma unroll
            for (int mt = 0; mt < 2; mt++)
                #pragma unroll
                for (int nt = 0; nt < 4; nt++)
                    mma_tf32(acc[mt][nt], a[mt], b[nt]);
        }
        __syncthreads();
    }
    #pragma unroll
    for (int mt = 0; mt < 2; mt++) {
        int r0 = wm + (mt << 4) + (lane >> 2);
        #pragma unroll
        for (int nt = 0; nt < 4; nt++) {
            int c = wn + (nt << 3) + ((lane & 3) << 1);
            float b0 = __ldg(&bias[c]), b1 = __ldg(&bias[c + 1]);
            hbuf[r0][c]         = acc[mt][nt][0] + b0;
            hbuf[r0][c + 1]     = acc[mt][nt][1] + b1;
            hbuf[r0 + 8][c]     = acc[mt][nt][2] + b0;
            hbuf[r0 + 8][c + 1] = acc[mt][nt][3] + b1;
        }
    }
    __syncthreads();
    const int head = lane >> 2, sub = lane & 3;
    const float* av = hop_att0 + head * CC + (sub << 2);
    const float av0 = av[0], av1 = av[1], av2 = av[2], av3 = av[3];
    const float* sv = atts1 + head * CC + (sub << 2);
    const float sv0 = sv[0], sv1 = sv[1], sv2 = sv[2], sv3 = sv[3];
    const float hb = hop_bias0[head];
    #pragma unroll
    for (int j = 0; j < 8; j++) {
        int row = (warp << 3) + j;
        int grow = block_row + row;
        if (grow < NN) {
            float4 h4 = *(float4*)&hbuf[row][lane << 2];
            float p = eluf(h4.x)*av0 + eluf(h4.y)*av1 + eluf(h4.z)*av2 + eluf(h4.w)*av3;
            p += __shfl_xor_sync(0xffffffffu, p, 1);
            p += __shfl_xor_sync(0xffffffffu, p, 2);
            float g = p + hb;
            size_t off = (size_t)grow * HC + (lane << 2);
            *(float4*)&g_hA[off] = h4;
            store_half4(&g_h16A[off], h4);
            float4 z4 = make_float4(h4.x*g, h4.y*g, h4.z*g, h4.w*g);
            *(float4*)&g_z[off] = z4;
            float4 zs4 = make_float4(z4.x*decay0, z4.y*decay0, z4.z*decay0, z4.w*decay0);
            store_half4(&g_zsh[off], zs4);
            float p2 = eluf(2.f*zs4.x)*sv0 + eluf(2.f*zs4.y)*sv1
                     + eluf(2.f*zs4.z)*sv2 + eluf(2.f*zs4.w)*sv3;
            p2 += __shfl_xor_sync(0xffffffffu, p2, 1);
            p2 += __shfl_xor_sync(0xffffffffu, p2, 2);
            if (sub == 0) {
                float a = softplusf(p2) + 1e-6f;
                g_aself[(size_t)grow * HH + head] = a;
                g_deg  [(size_t)grow * HH + head] = a;
            }
        }
    }
}

// ---------------- edge attention: HALF-warp per edge, 2 CONSECUTIVE pairs/iter -----
__global__ void edge_att_kernel(const float* __restrict__ atts_k)
{
    const int lane = threadIdx.x & 31;
    const int warp0 = (blockIdx.x * blockDim.x + threadIdx.x) >> 5;
    const int nwarps = (gridDim.x * blockDim.x) >> 5;
    const int half = lane >> 4;
    const int sl = lane & 15;
    const int head = sl >> 1;
    const float* av = atts_k + head * CC + ((sl & 1) << 3);
    float4 avl = *(const float4*)av;
    float4 avh = *(const float4*)(av + 4);

    const int NG2 = EE >> 2;   // 200000 groups of 4 consecutive edges
    for (int g2 = warp0; g2 < NG2; g2 += nwarps) {
        int p0 = (g2 << 2) + half;       // edges 4*g2 + {0,1}
        int p1 = p0 + 2;                 // edges 4*g2 + {2,3}
        int2 rc0 = __ldg(&g_edge[p0]);
        int2 rc1 = __ldg(&g_edge[p1]);
        const uint4 i0 = *(const uint4*)&g_zsh[((unsigned)rc0.y << 7) + (sl << 3)];
        const uint4 j0 = *(const uint4*)&g_zsh[((unsigned)rc0.x << 7) + (sl << 3)];
        const uint4 i1 = *(const uint4*)&g_zsh[((unsigned)rc1.y << 7) + (sl << 3)];
        const uint4 j1 = *(const uint4*)&g_zsh[((unsigned)rc1.x << 7) + (sl << 3)];
        // edge 0
        {
            __half2 s0 = __hadd2(*(__half2*)&i0.x, *(__half2*)&j0.x);
            __half2 s1 = __hadd2(*(__half2*)&i0.y, *(__half2*)&j0.y);
            __half2 s2 = __hadd2(*(__half2*)&i0.z, *(__half2*)&j0.z);
            __half2 s3 = __hadd2(*(__half2*)&i0.w, *(__half2*)&j0.w);
            float2 f0 = __half22float2(s0);
            float2 f1 = __half22float2(s1);
            float2 f2 = __half22float2(s2);
            float2 f3 = __half22float2(s3);
            float s = eluf(f0.x)*avl.x + eluf(f0.y)*avl.y
                    + eluf(f1.x)*avl.z + eluf(f1.y)*avl.w
                    + eluf(f2.x)*avh.x + eluf(f2.y)*avh.y
                    + eluf(f3.x)*avh.z + eluf(f3.y)*avh.w;
            s += __shfl_xor_sync(0xffffffffu, s, 1);
            if (!(sl & 1)) {
                float a = softplusf(s) + 1e-6f;
                g_ae[(size_t)p0 * HH + head] = a;
                atomicAdd(&g_deg[(size_t)rc0.y * HH + head], a);
            }
        }
        // edge 1
        {
            __half2 s0 = __hadd2(*(__half2*)&i1.x, *(__half2*)&j1.x);
            __half2 s1 = __hadd2(*(__half2*)&i1.y, *(__half2*)&j1.y);
            __half2 s2 = __hadd2(*(__half2*)&i1.z, *(__half2*)&j1.z);
            __half2 s3 = __hadd2(*(__half2*)&i1.w, *(__half2*)&j1.w);
            float2 f0 = __half22float2(s0);
            float2 f1 = __half22float2(s1);
            float2 f2 = __half22float2(s2);
            float2 f3 = __half22float2(s3);
            float s = eluf(f0.x)*avl.x + eluf(f0.y)*avl.y
                    + eluf(f1.x)*avl.z + eluf(f1.y)*avl.w
                    + eluf(f2.x)*avh.x + eluf(f2.y)*avh.y
                    + eluf(f3.x)*avh.z + eluf(f3.y)*avh.w;
            s += __shfl_xor_sync(0xffffffffu, s, 1);
            if (!(sl & 1)) {
                float a = softplusf(s) + 1e-6f;
                g_ae[(size_t)p1 * HH + head] = a;
                atomicAdd(&g_deg[(size_t)rc1.y * HH + head], a);
            }
        }
    }
}

// ---------------- dinv = rsqrt(deg) -------------------------------------------------
__global__ void dinv_kernel()
{
    int i = blockIdx.x * blockDim.x + threadIdx.x;
    if (i < NN * HH) g_dinv[i] = rsqrtf(g_deg[i]);
}

// ---------------- propagate + hop update (fused; fp16 gathers, unroll 8) -----------
__global__ void prop_fused(const float* __restrict__ hop_atts_k,
                           const float* __restrict__ hop_bias_k,
                           const float* __restrict__ atts_next,
                           float decay_prev, float decayk, int flip, int do_next)
{
    const float*  hp   = flip ? g_hA   : g_hB;
    const __half* hp16 = flip ? g_h16A : g_h16B;
    float*  hout   = flip ? g_hB   : g_hA;
    __half* hout16 = flip ? g_h16B : g_h16A;
    int w = (blockIdx.x * blockDim.x + threadIdx.x) >> 5;
    if (w >= NN) return;
    const int lane = threadIdx.x & 31;
    const int head = lane >> 2, sub = lane & 3;
    const unsigned coff = ((unsigned)w << 7) + (lane << 2);

    float dinv_c = g_dinv[w * HH + head];
    float asn = g_aself[w * HH + head] * dinv_c;
    float4 hc = *(const float4*)&hp[coff];
    float4 acc = make_float4(asn*hc.x, asn*hc.y, asn*hc.z, asn*hc.w);

    const int beg = g_off[w], end = g_off[w + 1];
    int p = beg;
    for (; p + 7 < end; p += 8) {
        int rr[8];
        #pragma unroll
        for (int u = 0; u < 8; u++) rr[u] = __ldg(&g_src[p + u]);
        uint2 hv[8];
        #pragma unroll
        for (int u = 0; u < 8; u++)
            hv[u] = *(const uint2*)&hp16[((unsigned)rr[u] << 7) + (lane << 2)];
        float aa[8];
        #pragma unroll
        for (int u = 0; u < 8; u++)
            aa[u] = __ldg(&g_ae[(size_t)(p + u) * HH + head])
                  * __ldg(&g_dinv[rr[u] * HH + head]);
        #pragma unroll
        for (int u = 0; u < 8; u++) {
            float2 lo = __half22float2(*(__half2*)&hv[u].x);
            float2 hi = __half22float2(*(__half2*)&hv[u].y);
            acc.x = fmaf(aa[u], lo.x, acc.x); acc.y = fmaf(aa[u], lo.y, acc.y);
            acc.z = fmaf(aa[u], hi.x, acc.z); acc.w = fmaf(aa[u], hi.y, acc.w);
        }
    }
    for (; p < end; p++) {
        int r0 = __ldg(&g_src[p]);
        float a0 = __ldg(&g_ae[(size_t)p * HH + head]) * __ldg(&g_dinv[r0 * HH + head]);
        float4 h0 = load_half4(&hp16[((unsigned)r0 << 7) + (lane << 2)]);
        acc.x = fmaf(a0, h0.x, acc.x); acc.y = fmaf(a0, h0.y, acc.y);
        acc.z = fmaf(a0, h0.z, acc.z); acc.w = fmaf(a0, h0.w, acc.w);
    }

    float4 h4 = make_float4(acc.x*dinv_c, acc.y*dinv_c, acc.z*dinv_c, acc.w*dinv_c);
    *(float4*)&hout[coff] = h4;
    store_half4(&hout16[coff], h4);

    // hop attention + z update
    float4 z4 = *(const float4*)&g_z[coff];
    float4 zp = make_float4(z4.x*decay_prev, z4.y*decay_prev,
                            z4.z*decay_prev, z4.w*decay_prev);
    const float* aw  = hop_atts_k + head * (2 * CC) + (sub << 2);
    const float* aw2 = aw + CC;
    float s = eluf(h4.x)*aw[0]  + eluf(h4.y)*aw[1]  + eluf(h4.z)*aw[2]  + eluf(h4.w)*aw[3]
            + eluf(zp.x)*aw2[0] + eluf(zp.y)*aw2[1] + eluf(zp.z)*aw2[2] + eluf(zp.w)*aw2[3];
    s += __shfl_xor_sync(0xffffffffu, s, 1);
    s += __shfl_xor_sync(0xffffffffu, s, 2);
    float g = s + hop_bias_k[head];
    z4.x = fmaf(h4.x, g, z4.x);
    z4.y = fmaf(h4.y, g, z4.y);
    z4.z = fmaf(h4.z, g, z4.z);
    z4.w = fmaf(h4.w, g, z4.w);
    *(float4*)&g_z[coff] = z4;
    float4 zs4 = make_float4(z4.x*decayk, z4.y*decayk, z4.z*decayk, z4.w*decayk);
    store_half4(&g_zsh[coff], zs4);

    if (do_next) {
        const float* sv = atts_next + head * CC + (sub << 2);
        float p2 = eluf(2.f*zs4.x)*sv[0] + eluf(2.f*zs4.y)*sv[1]
                 + eluf(2.f*zs4.z)*sv[2] + eluf(2.f*zs4.w)*sv[3];
        p2 += __shfl_xor_sync(0xffffffffu, p2, 1);
        p2 += __shfl_xor_sync(0xffffffffu, p2, 2);
        if (sub == 0) {
            float a = softplusf(p2) + 1e-6f;
            g_aself[w * HH + head] = a;
            g_deg  [w * HH + head] = a;
        }
    }
}

// ---------------- output: out = elu(z) @ Wout + bout  (N x 40) --------------------
__global__ void out_kernel(const float* __restrict__ Wout,
                           const float* __restrict__ bout,
                           float* __restrict__ out)
{
    __shared__ float Ws[HC * 40];
    __shared__ float bs[40];
    __shared__ float zsm[8][HC];
    int tid = threadIdx.x;
    for (int i = tid; i < HC * 40; i += 320) Ws[i] = Wout[i];
    if (tid < 40) bs[tid] = bout[tid];
    int nbase = blockIdx.x * 8;
    for (int i = tid; i < 8 * HC; i += 320) {
        int ln = i >> 7, c = i & 127;
        int gn = nbase + ln;
        float v = (gn < NN) ? g_z[(size_t)gn * HC + c] : 0.f;
        zsm[ln][c] = eluf(v);
    }
    __syncthreads();
    int ln = tid / 40, o = tid % 40;
    if (ln < 8) {
        int gn = nbase + ln;
        if (gn < NN) {
            float acc = bs[o];
            #pragma unroll 8
            for (int c = 0; c < HC; c++) acc = fmaf(zsm[ln][c], Ws[c * 40 + o], acc);
            out[(size_t)gn * 40 + o] = acc;
        }
    }
}

// ---------------- host orchestration ----------------------------------------------
extern "C" void kernel_launch(void* const* d_in, const int* in_sizes, int n_in,
                              void* d_out, int out_size)
{
    const float* x          = (const float*)d_in[0];
    const int*   ei         = (const int*)d_in[1];
    const float* W0         = (const float*)d_in[2];
    const float* b0         = (const float*)d_in[3];
    const float* W1         = (const float*)d_in[4];
    const float* b1         = (const float*)d_in[5];
    const float* Wout       = (const float*)d_in[6];
    const float* bout       = (const float*)d_in[7];
    const float* hop_att0   = (const float*)d_in[8];
    const float* hop_atts   = (const float*)d_in[9];
    const float* atts       = (const float*)d_in[10];
    const float* hop_biases = (const float*)d_in[11];
    float* out = (float*)d_out;

    float decay[5];
    for (int k = 0; k <= 4; k++) decay[k] = (float)log(1.0 / (k + 1) + 1.0 + 1e-6);

    const int NODE_GRID = (NN + 7) / 8;          // warp per node, 8 warps/block
    const int EDGE_GRID = 12500;                 // 100k warps; 2 groups of 4 each

    hist_kernel<<<1024, 256>>>(ei);                                  // idx 0
    scan_kernel<<<1, 1024>>>();                                      // idx 1
    gemm1_tc<<<(NN + 127) / 128, 256>>>(x, W0, b0);                  // idx 2
    gemm2_tc<<<(NN + 63) / 64, 256>>>(W1, b1, hop_att0, hop_biases,
                                      atts, decay[0]);               // idx 3 (profiled)
    scatter_kernel<<<1024, 256>>>(ei);                               // idx 4

    for (int k = 1; k <= 4; k++) {
        int flip = (k & 1);
        edge_att_kernel<<<EDGE_GRID, 256>>>(atts + (size_t)(k - 1) * HH * CC);
        dinv_kernel<<<(NN * HH + 255) / 256, 256>>>();
        prop_fused<<<NODE_GRID, 256>>>(hop_atts + (size_t)(k - 1) * HH * 2 * CC,
                                       hop_biases + (size_t)k * HH,
                                       atts + (size_t)k * HH * CC,
                                       decay[k - 1], decay[k], flip,
                                       (k < 4) ? 1 : 0);
    }

    out_kernel<<<(NN + 7) / 8, 320>>>(Wout, bout, out);
}